// round 15
// baseline (speedup 1.0000x reference)
#include <cuda_runtime.h>
#include <cuda_bf16.h>
#include <math.h>
#include <stdint.h>

#define BB   2
#define TT   16
#define NN   2048
#define CI1  32
#define CHH  64
#define EE   32768
#define T1   14
#define T2   12
#define F1   (BB*T1*CHH)
#define F14  (F1/4)
#define NB_TOTAL (NN*BB)

__device__ __forceinline__ uint32_t pkbf2(float a, float b) {
    __nv_bfloat162 h = __floats2bfloat162_rn(a, b);
    return *reinterpret_cast<uint32_t*>(&h);
}
__device__ __forceinline__ void mma_bf16(float* d, const uint32_t* a,
                                         uint32_t b0, uint32_t b1) {
    asm volatile(
        "mma.sync.aligned.m16n8k16.row.col.f32.bf16.bf16.f32 "
        "{%0,%1,%2,%3}, {%4,%5,%6,%7}, {%8,%9}, {%0,%1,%2,%3};"
        : "+f"(d[0]), "+f"(d[1]), "+f"(d[2]), "+f"(d[3])
        : "r"(a[0]), "r"(a[1]), "r"(a[2]), "r"(a[3]), "r"(b0), "r"(b1));
}

// ---------------- scratch ----------------------------------------------------
__device__ __align__(16) float g_t1 [NB_TOTAL*T1*CHH];
__device__ __align__(16) float g_tx1[NB_TOTAL*T1*CHH];
__device__ __align__(16) float g_tx2[NB_TOTAL*T1*CHH];
__device__ __align__(16) float g_t2 [NB_TOTAL*T1*CHH];
__device__ float g_deg[NN];
__device__ float g_dis[NN];
__device__ int   g_rowcount[NN];
__device__ int   g_rowstart[NN+1];
__device__ int   g_cursor[NN];
__device__ int   g_ccol[EE];
__device__ float g_cnorm[EE];
__device__ int   g_barc = 0;
// fragment-order packed B weights (uint2 {b0,b1} per (ntile, ks, lane)):
__device__ __align__(16) uint2 g_bh[3*24*4*32];
__device__ __align__(16) uint2 g_bl[3*24*4*32];
__device__ __align__(16) uint2 g_b1h[24*6*32];
__device__ __align__(16) uint2 g_b1l[24*6*32];
__device__ __align__(16) uint2 g_chh[3*8*4*32];
__device__ __align__(16) uint2 g_chl[3*8*4*32];

// ---------------- fused multi-block preprocessing with spin barrier ----------
__device__ __forceinline__ void gbar(int target) {
    __syncthreads();
    if (threadIdx.x == 0) {
        __threadfence();
        atomicAdd(&g_barc, 1);
        while (*(volatile int*)&g_barc < target) {}
        __threadfence();
    }
    __syncthreads();
}

__global__ void __launch_bounds__(256) k_prep(const int* __restrict__ ei,
                                              const float* __restrict__ ew) {
    __shared__ int wsum[8];
    __shared__ int woffs[8];
    int tid = threadIdx.x, bid = blockIdx.x;
    int gt = bid * 256 + tid;                 // 0..32767 (== EE)
    // P0: zero
    for (int i = gt; i < NN; i += 32768) { g_deg[i] = 0.f; g_rowcount[i] = 0; g_cursor[i] = 0; }
    gbar(128);
    // P1: degree + counts
    {
        int r = ei[gt], c = ei[EE + gt];
        float w = (r == c) ? 0.f : ew[gt];
        atomicAdd(&g_deg[r], w);
        atomicAdd(&g_rowcount[r], 1);
    }
    gbar(256);
    // P2: block 0 computes dis + prefix scan
    if (bid == 0) {
        for (int i = tid; i < NN; i += 256) {
            float d = g_deg[i];
            g_dis[i] = (d > 0.f) ? rsqrtf(d) : 0.f;
        }
        int v[8]; int ls = 0;
        int base = tid * 8;
#pragma unroll
        for (int u = 0; u < 8; u++) { v[u] = g_rowcount[base + u]; ls += v[u]; }
        int lane = tid & 31, wid = tid >> 5;
        int inc = ls;
#pragma unroll
        for (int o = 1; o < 32; o <<= 1) {
            int t = __shfl_up_sync(0xffffffffu, inc, o);
            if (lane >= o) inc += t;
        }
        if (lane == 31) wsum[wid] = inc;
        __syncthreads();
        if (tid == 0) { int r = 0; for (int w2 = 0; w2 < 8; w2++) { woffs[w2] = r; r += wsum[w2]; } }
        __syncthreads();
        int run = woffs[wid] + inc - ls;
#pragma unroll
        for (int u = 0; u < 8; u++) { run += v[u]; g_rowstart[base + u + 1] = run; }
        if (tid == 0) g_rowstart[0] = 0;
    }
    gbar(384);
    // P3: scatter
    {
        int r = ei[gt], c = ei[EE + gt];
        float w = (r == c) ? 0.f : ew[gt];
        int pos = g_rowstart[r] + atomicAdd(&g_cursor[r], 1);
        g_ccol[pos]  = c;
        g_cnorm[pos] = -g_dis[r] * w * g_dis[c];
    }
    gbar(512);
    if (bid == 0 && tid == 0) g_barc = 0;   // reset for next graph replay
}

// ---------------- weight prep: pack B into mma fragment order ----------------
__global__ void k_wprep(const float* __restrict__ w1, const float* __restrict__ w2,
                        const float* __restrict__ w3,
                        const float* __restrict__ v1, const float* __restrict__ v2,
                        const float* __restrict__ v3,
                        const float* __restrict__ cw) {
    int idx = blockIdx.x * blockDim.x + threadIdx.x;
    if (idx < 9216) {                               // tconv2
        int lane = idx & 31;
        int rest = idx >> 5;
        int ks = rest & 3; rest >>= 2;
        int nti = rest % 24;
        int kc  = rest / 24;
        int n  = nti * 8 + (lane >> 2);
        int k0 = ks * 16 + 2 * (lane & 3);
        int j = n / 64, co = n % 64;
        const float* wj = (j == 0) ? w1 : ((j == 1) ? w2 : w3);
        float v00 = wj[(co * 64 + k0    ) * 3 + kc];
        float v01 = wj[(co * 64 + k0 + 1) * 3 + kc];
        float v10 = wj[(co * 64 + k0 + 8) * 3 + kc];
        float v11 = wj[(co * 64 + k0 + 9) * 3 + kc];
        float h00 = __bfloat162float(__float2bfloat16(v00));
        float h01 = __bfloat162float(__float2bfloat16(v01));
        float h10 = __bfloat162float(__float2bfloat16(v10));
        float h11 = __bfloat162float(__float2bfloat16(v11));
        g_bh[idx] = make_uint2(pkbf2(h00, h01), pkbf2(h10, h11));
        g_bl[idx] = make_uint2(pkbf2(v00 - h00, v01 - h01), pkbf2(v10 - h10, v11 - h11));
    }
    int i1 = idx - 9216;                            // tconv1
    if (i1 >= 0 && i1 < 4608) {
        int lane = i1 & 31;
        int rest = i1 >> 5;
        int ks = rest % 6;
        int nti = rest / 6;
        int n  = nti * 8 + (lane >> 2);
        int k0 = ks * 16 + 2 * (lane & 3);
        int j = n / 64, co = n % 64;
        const float* wj = (j == 0) ? v1 : ((j == 1) ? v2 : v3);
        float vv[4];
#pragma unroll
        for (int u = 0; u < 4; u++) {
            int k = k0 + (u >> 1) * 8 + (u & 1);
            int tap = k >> 5, ci = k & 31;
            vv[u] = wj[(co * 32 + ci) * 3 + tap];
        }
        float h0 = __bfloat162float(__float2bfloat16(vv[0]));
        float h1 = __bfloat162float(__float2bfloat16(vv[1]));
        float h2 = __bfloat162float(__float2bfloat16(vv[2]));
        float h3 = __bfloat162float(__float2bfloat16(vv[3]));
        g_b1h[i1] = make_uint2(pkbf2(h0, h1), pkbf2(h2, h3));
        g_b1l[i1] = make_uint2(pkbf2(vv[0] - h0, vv[1] - h1), pkbf2(vv[2] - h2, vv[3] - h3));
    }
    int i2 = i1 - 4608;                             // cheb
    if (i2 >= 0 && i2 < 3072) {
        int lane = i2 & 31;
        int rest = i2 >> 5;
        int ks = rest & 3; rest >>= 2;
        int nti = rest % 8;
        int jj  = rest / 8;
        int co = nti * 8 + (lane >> 2);
        int k0 = ks * 16 + 2 * (lane & 3);
        float v00 = cw[(jj * 64 + k0    ) * 64 + co];
        float v01 = cw[(jj * 64 + k0 + 1) * 64 + co];
        float v10 = cw[(jj * 64 + k0 + 8) * 64 + co];
        float v11 = cw[(jj * 64 + k0 + 9) * 64 + co];
        float h00 = __bfloat162float(__float2bfloat16(v00));
        float h01 = __bfloat162float(__float2bfloat16(v01));
        float h10 = __bfloat162float(__float2bfloat16(v10));
        float h11 = __bfloat162float(__float2bfloat16(v11));
        g_chh[i2] = make_uint2(pkbf2(h00, h01), pkbf2(h10, h11));
        g_chl[i2] = make_uint2(pkbf2(v00 - h00, v01 - h01), pkbf2(v10 - h10, v11 - h11));
    }
}

// =============================================================================
// tconv1 HMMA (R14 proven): M=57344, N=192, K=96; packed-B LDS.64.
// =============================================================================
#define AP1 104
#define O1_AH   768
#define O1_AL   (O1_AH + 128*AP1*2)
#define O1_BH   (O1_AL + 128*AP1*2)
#define O1_BL   (O1_BH + 36864)
#define SMEM_H1 (O1_BL + 36864)

__global__ void __launch_bounds__(512, 1) k_tconv1_hmma(
    const float* __restrict__ x,
    const float* __restrict__ bb1, const float* __restrict__ bb2,
    const float* __restrict__ bb3)
{
    extern __shared__ char smem[];
    float*         sbias = (float*)smem;
    __nv_bfloat16* sAh   = (__nv_bfloat16*)(smem + O1_AH);
    __nv_bfloat16* sAl   = (__nv_bfloat16*)(smem + O1_AL);
    const uint2*   uBH   = (const uint2*)(smem + O1_BH);
    const uint2*   uBL   = (const uint2*)(smem + O1_BL);

    int tid = threadIdx.x;
    if (tid < 64) {
        sbias[tid]       = bb1[tid];
        sbias[64 + tid]  = bb2[tid];
        sbias[128 + tid] = bb3[tid];
    }

    {
        int rA = tid >> 2, quarter = tid & 3;
        long R = (long)blockIdx.x * 128 + rA;
        int nb = (int)(R / 14), t = (int)(R % 14);
        int b = nb & 1, n = nb >> 1;
        const float* xb = x + (long)b * (TT * NN * CI1) + (long)n * CI1;
#pragma unroll
        for (int k4 = 0; k4 < 6; k4++) {
            int k = quarter * 24 + k4 * 4;
            int tap = k >> 5, ci = k & 31;
            float4 v = __ldg((const float4*)(xb + (long)(t + tap) * (NN * CI1) + ci));
            float hx = __bfloat162float(__float2bfloat16(v.x));
            float hy = __bfloat162float(__float2bfloat16(v.y));
            float hz = __bfloat162float(__float2bfloat16(v.z));
            float hw = __bfloat162float(__float2bfloat16(v.w));
            uint32_t off = (uint32_t)rA * (AP1 * 2) + k * 2;
            *(uint2*)((char*)sAh + off) = make_uint2(pkbf2(hx, hy), pkbf2(hz, hw));
            *(uint2*)((char*)sAl + off) = make_uint2(pkbf2(v.x - hx, v.y - hy),
                                                     pkbf2(v.z - hz, v.w - hw));
        }
    }
    for (int u = tid; u < 2304; u += 512) {
        ((uint4*)(smem + O1_BH))[u] = ((const uint4*)g_b1h)[u];
        ((uint4*)(smem + O1_BL))[u] = ((const uint4*)g_b1l)[u];
    }
    __syncthreads();

    int lane = tid & 31, w = tid >> 5;
    int m0 = (w >> 1) * 16;
    int c0 = (w & 1) * 32;
    int g  = lane >> 2, tg = lane & 3;

    float acc[12][4];
#pragma unroll
    for (int nt = 0; nt < 12; nt++)
#pragma unroll
        for (int q = 0; q < 4; q++) acc[nt][q] = 0.f;

#pragma unroll
    for (int ks = 0; ks < 6; ks++) {
        uint32_t ah[4], al[4];
        {
            int row = m0 + g;
            const __nv_bfloat16* ph = sAh + row * AP1 + ks * 16 + 2 * tg;
            const __nv_bfloat16* pl = sAl + row * AP1 + ks * 16 + 2 * tg;
            ah[0] = *(const uint32_t*)(ph);
            ah[1] = *(const uint32_t*)(ph + 8 * AP1);
            ah[2] = *(const uint32_t*)(ph + 8);
            ah[3] = *(const uint32_t*)(ph + 8 * AP1 + 8);
            al[0] = *(const uint32_t*)(pl);
            al[1] = *(const uint32_t*)(pl + 8 * AP1);
            al[2] = *(const uint32_t*)(pl + 8);
            al[3] = *(const uint32_t*)(pl + 8 * AP1 + 8);
        }
#pragma unroll
        for (int nt = 0; nt < 12; nt++) {
            int nti = (nt >> 2) * 8 + (c0 >> 3) + (nt & 3);
            uint2 bh = uBH[(nti * 6 + ks) * 32 + lane];
            uint2 bl = uBL[(nti * 6 + ks) * 32 + lane];
            mma_bf16(acc[nt], ah, bh.x, bh.y);
            mma_bf16(acc[nt], ah, bl.x, bl.y);
            mma_bf16(acc[nt], al, bh.x, bh.y);
        }
    }

#pragma unroll
    for (int rs = 0; rs < 2; rs++) {
        int row = m0 + g + rs * 8;
        long R = (long)blockIdx.x * 128 + row;
        int nb = (int)(R / 14), t = (int)(R % 14);
        float* orow = g_t1 + ((long)nb * T1 + t) * 64;
#pragma unroll
        for (int cb = 0; cb < 4; cb++) {
            int col = c0 + cb * 8 + 2 * tg;
#pragma unroll
            for (int qq = 0; qq < 2; qq++) {
                float a1 = acc[cb][rs * 2 + qq]     + sbias[col + qq];
                float a2 = acc[4 + cb][rs * 2 + qq] + sbias[64 + col + qq];
                float a3 = acc[8 + cb][rs * 2 + qq] + sbias[128 + col + qq];
                float sg = __fdividef(1.f, 1.f + __expf(-a2));
                float v  = a1 + sg + a3;
                orow[col + qq] = (v > 0.f) ? v : 0.f;
            }
        }
    }
}

// =============================================================================
// tconv2 + fused BN: M=49152 tiled 96 (=4 whole nodes/block), N=192.
// 384 thr = 12 warps (6 m-tiles x 2 c-halves). BN stats in-block, write d_out.
// =============================================================================
#define AP2 72
#define O2_ST   768
#define O2_AH   1024
#define O2_AL   (O2_AH + 96*AP2*2)     /* 14848 */
#define O2_BH   (O2_AL + 96*AP2*2)     /* 28672 */
#define O2_BL   (O2_BH + 24576)        /* 53248 */
#define SMEM_B2 (O2_BL + 24576)        /* 77824 */

__global__ void __launch_bounds__(384, 1) k_tconv2_bn(
    const float* __restrict__ bb1, const float* __restrict__ bb2,
    const float* __restrict__ bb3,
    const float* __restrict__ gamma, const float* __restrict__ beta,
    float* __restrict__ out)
{
    extern __shared__ char smem[];
    float*         sbias = (float*)smem;
    float*         sstat = (float*)(smem + O2_ST);   // [0..3]=sum [4..7]=sq [8..11]=mu [12..15]=rstd
    __nv_bfloat16* sAh   = (__nv_bfloat16*)(smem + O2_AH);
    __nv_bfloat16* sAl   = (__nv_bfloat16*)(smem + O2_AL);
    const uint2*   uBH   = (const uint2*)(smem + O2_BH);
    const uint2*   uBL   = (const uint2*)(smem + O2_BL);

    int tid = threadIdx.x;
    if (tid < 64) {
        sbias[tid]       = bb1[tid];
        sbias[64 + tid]  = bb2[tid];
        sbias[128 + tid] = bb3[tid];
    }
    if (tid < 8) sstat[tid] = 0.f;

    int lane = tid & 31, w = tid >> 5;
    int m0 = (w >> 1) * 16;
    int c0 = (w & 1) * 32;
    int g  = lane >> 2, tg = lane & 3;

    int rA = tid >> 2, quarter = tid & 3;
    long RA = (long)blockIdx.x * 96 + rA;
    int nbA = (int)(RA / 12), tA = (int)(RA % 12);

    float acc[12][4];
#pragma unroll
    for (int nt = 0; nt < 12; nt++)
#pragma unroll
        for (int q = 0; q < 4; q++) acc[nt][q] = 0.f;

    for (int kc = 0; kc < 3; kc++) {
        __syncthreads();
        {
            const float4* src = (const float4*)(g_t2 + ((long)nbA * T1 + tA + kc) * 64)
                                + quarter * 4;
            uint32_t off = (uint32_t)rA * (AP2 * 2) + quarter * 32;
            uint2* dh = (uint2*)((char*)sAh + off);
            uint2* dl = (uint2*)((char*)sAl + off);
#pragma unroll
            for (int v4 = 0; v4 < 4; v4++) {
                float4 xv = __ldg(&src[v4]);
                float hx = __bfloat162float(__float2bfloat16(xv.x));
                float hy = __bfloat162float(__float2bfloat16(xv.y));
                float hz = __bfloat162float(__float2bfloat16(xv.z));
                float hw = __bfloat162float(__float2bfloat16(xv.w));
                dh[v4] = make_uint2(pkbf2(hx, hy), pkbf2(hz, hw));
                dl[v4] = make_uint2(pkbf2(xv.x - hx, xv.y - hy),
                                    pkbf2(xv.z - hz, xv.w - hw));
            }
        }
        {
            const uint4* bh = (const uint4*)(g_bh + (long)kc * 3072);
            const uint4* bl = (const uint4*)(g_bl + (long)kc * 3072);
            for (int u = tid; u < 1536; u += 384) {
                ((uint4*)(smem + O2_BH))[u] = bh[u];
                ((uint4*)(smem + O2_BL))[u] = bl[u];
            }
        }
        __syncthreads();

#pragma unroll
        for (int ks = 0; ks < 4; ks++) {
            uint32_t ah[4], al[4];
            {
                int row = m0 + g;
                const __nv_bfloat16* ph = sAh + row * AP2 + ks * 16 + 2 * tg;
                const __nv_bfloat16* pl = sAl + row * AP2 + ks * 16 + 2 * tg;
                ah[0] = *(const uint32_t*)(ph);
                ah[1] = *(const uint32_t*)(ph + 8 * AP2);
                ah[2] = *(const uint32_t*)(ph + 8);
                ah[3] = *(const uint32_t*)(ph + 8 * AP2 + 8);
                al[0] = *(const uint32_t*)(pl);
                al[1] = *(const uint32_t*)(pl + 8 * AP2);
                al[2] = *(const uint32_t*)(pl + 8);
                al[3] = *(const uint32_t*)(pl + 8 * AP2 + 8);
            }
#pragma unroll
            for (int nt = 0; nt < 12; nt++) {
                int nti = (nt >> 2) * 8 + (c0 >> 3) + (nt & 3);
                uint2 bh = uBH[(nti * 4 + ks) * 32 + lane];
                uint2 bl = uBL[(nti * 4 + ks) * 32 + lane];
                mma_bf16(acc[nt], ah, bh.x, bh.y);
                mma_bf16(acc[nt], ah, bl.x, bl.y);
                mma_bf16(acc[nt], al, bh.x, bh.y);
            }
        }
    }

    // ---- gated epilogue in registers + per-node BN stats ----
    float vv[2][4][2];
#pragma unroll
    for (int rs = 0; rs < 2; rs++) {
        int row = m0 + g + rs * 8;
        float s = 0.f, ss = 0.f;
#pragma unroll
        for (int cb = 0; cb < 4; cb++) {
            int col = c0 + cb * 8 + 2 * tg;
#pragma unroll
            for (int qq = 0; qq < 2; qq++) {
                float a1 = acc[cb][rs * 2 + qq]     + sbias[col + qq];
                float a2 = acc[4 + cb][rs * 2 + qq] + sbias[64 + col + qq];
                float a3 = acc[8 + cb][rs * 2 + qq] + sbias[128 + col + qq];
                float sg = __fdividef(1.f, 1.f + __expf(-a2));
                float v  = a1 + sg + a3;
                v = (v > 0.f) ? v : 0.f;
                vv[rs][cb][qq] = v;
                s += v; ss += v * v;
            }
        }
        s  += __shfl_xor_sync(0xffffffffu, s, 1);
        s  += __shfl_xor_sync(0xffffffffu, s, 2);
        ss += __shfl_xor_sync(0xffffffffu, ss, 1);
        ss += __shfl_xor_sync(0xffffffffu, ss, 2);
        if (tg == 0) {
            int nl = row / 24;
            atomicAdd(&sstat[nl], s);
            atomicAdd(&sstat[4 + nl], ss);
        }
    }
    __syncthreads();
    if (tid < 4) {
        float mu  = sstat[tid] * (1.f / 1536.f);
        float var = sstat[4 + tid] * (1.f / 1536.f) - mu * mu;
        sstat[8 + tid]  = mu;
        sstat[12 + tid] = rsqrtf(var + 1e-5f);
    }
    __syncthreads();

#pragma unroll
    for (int rs = 0; rs < 2; rs++) {
        int row = m0 + g + rs * 8;
        long R = (long)blockIdx.x * 96 + row;
        int nb = (int)(R / 12), t = (int)(R % 12);
        int ng = (int)(R / 24);
        int b  = nb & 1;
        int nl = row / 24;
        float mu = sstat[8 + nl], rstd = sstat[12 + nl];
        float ga = __ldg(&gamma[ng]), be = __ldg(&beta[ng]);
        float scale = rstd * ga;
        float* orow = out + (((long)b * T2 + t) * NN + ng) * 64;
#pragma unroll
        for (int cb = 0; cb < 4; cb++) {
            int col = c0 + cb * 8 + 2 * tg;
            float o0 = (vv[rs][cb][0] - mu) * scale + be;
            float o1 = (vv[rs][cb][1] - mu) * scale + be;
            *(float2*)(orow + col) = make_float2(o0, o1);
        }
    }
}

// =============================================================================
// cheb HMMA (R14 proven): M=57344, N=64, K=3 j x 64; block tile M=256.
// =============================================================================
#define APC 72
#define OC_AH   256
#define OC_AL   (OC_AH + 256*APC*2)
#define OC_BH   (OC_AL + 256*APC*2)
#define OC_BL   (OC_BH + 8192)
#define SMEM_HC (OC_BL + 8192)

__global__ void __launch_bounds__(512, 1) k_cheb_hmma(const float* __restrict__ bias)
{
    extern __shared__ char smem[];
    float*         sbias = (float*)smem;
    __nv_bfloat16* sAh   = (__nv_bfloat16*)(smem + OC_AH);
    __nv_bfloat16* sAl   = (__nv_bfloat16*)(smem + OC_AL);
    const uint2*   uBH   = (const uint2*)(smem + OC_BH);
    const uint2*   uBL   = (const uint2*)(smem + OC_BL);

    int tid = threadIdx.x;
    if (tid < 64) sbias[tid] = bias[tid];

    int lane = tid & 31, w = tid >> 5;
    int m0 = w * 16;
    int g  = lane >> 2, tg = lane & 3;

    int rA = tid >> 1, half = tid & 1;
    long RA = (long)blockIdx.x * 256 + rA;

    float acc[8][4];
#pragma unroll
    for (int nt = 0; nt < 8; nt++)
#pragma unroll
        for (int q = 0; q < 4; q++) acc[nt][q] = 0.f;

    for (int j = 0; j < 3; j++) {
        __syncthreads();
        {
            const float* srcj = (j == 0) ? g_t1 : ((j == 1) ? g_tx1 : g_tx2);
            const float4* src = (const float4*)(srcj + RA * 64) + half * 8;
            uint32_t off = (uint32_t)rA * (APC * 2) + half * 64;
            uint2* dh = (uint2*)((char*)sAh + off);
            uint2* dl = (uint2*)((char*)sAl + off);
#pragma unroll
            for (int v4 = 0; v4 < 8; v4++) {
                float4 xv = __ldg(&src[v4]);
                float hx = __bfloat162float(__float2bfloat16(xv.x));
                float hy = __bfloat162float(__float2bfloat16(xv.y));
                float hz = __bfloat162float(__float2bfloat16(xv.z));
                float hw = __bfloat162float(__float2bfloat16(xv.w));
                dh[v4] = make_uint2(pkbf2(hx, hy), pkbf2(hz, hw));
                dl[v4] = make_uint2(pkbf2(xv.x - hx, xv.y - hy),
                                    pkbf2(xv.z - hz, xv.w - hw));
            }
        }
        if (tid < 512) {
            ((uint4*)(smem + OC_BH))[tid] = ((const uint4*)(g_chh + (long)j * 1024))[tid];
            ((uint4*)(smem + OC_BL))[tid] = ((const uint4*)(g_chl + (long)j * 1024))[tid];
        }
        __syncthreads();

#pragma unroll
        for (int ks = 0; ks < 4; ks++) {
            uint32_t ah[4], al[4];
            {
                int row = m0 + g;
                const __nv_bfloat16* ph = sAh + row * APC + ks * 16 + 2 * tg;
                const __nv_bfloat16* pl = sAl + row * APC + ks * 16 + 2 * tg;
                ah[0] = *(const uint32_t*)(ph);
                ah[1] = *(const uint32_t*)(ph + 8 * APC);
                ah[2] = *(const uint32_t*)(ph + 8);
                ah[3] = *(const uint32_t*)(ph + 8 * APC + 8);
                al[0] = *(const uint32_t*)(pl);
                al[1] = *(const uint32_t*)(pl + 8 * APC);
                al[2] = *(const uint32_t*)(pl + 8);
                al[3] = *(const uint32_t*)(pl + 8 * APC + 8);
            }
#pragma unroll
            for (int nt = 0; nt < 8; nt++) {
                uint2 bh = uBH[(nt * 4 + ks) * 32 + lane];
                uint2 bl = uBL[(nt * 4 + ks) * 32 + lane];
                mma_bf16(acc[nt], ah, bh.x, bh.y);
                mma_bf16(acc[nt], ah, bl.x, bl.y);
                mma_bf16(acc[nt], al, bh.x, bh.y);
            }
        }
    }

#pragma unroll
    for (int rs = 0; rs < 2; rs++) {
        int row = m0 + g + rs * 8;
        long R = (long)blockIdx.x * 256 + row;
        float* orow = g_t2 + R * 64;
#pragma unroll
        for (int nt = 0; nt < 8; nt++) {
            int col = nt * 8 + 2 * tg;
            float v0 = acc[nt][rs * 2 + 0] + sbias[col];
            float v1 = acc[nt][rs * 2 + 1] + sbias[col + 1];
            v0 = (v0 > 0.f) ? v0 : 0.f;
            v1 = (v1 > 0.f) ? v1 : 0.f;
            *(float2*)(orow + col) = make_float2(v0, v1);
        }
    }
}

// ---------------- ChebConv propagation (CSR gather, 4x edge unroll) ----------
__global__ void k_prop(const float4* __restrict__ z, float4* __restrict__ out,
                       const float4* __restrict__ x0, int mode)
{
    int n = blockIdx.x;
    int tid = threadIdx.x;
    int e0 = g_rowstart[n], e1 = g_rowstart[n + 1];
    float4 acc = make_float4(0.f, 0.f, 0.f, 0.f);
    int e = e0;
    for (; e + 3 < e1; e += 4) {
        int   c0 = __ldg(&g_ccol[e]),     c1 = __ldg(&g_ccol[e + 1]);
        int   c2 = __ldg(&g_ccol[e + 2]), c3 = __ldg(&g_ccol[e + 3]);
        float n0 = __ldg(&g_cnorm[e]),    n1 = __ldg(&g_cnorm[e + 1]);
        float n2 = __ldg(&g_cnorm[e + 2]), n3 = __ldg(&g_cnorm[e + 3]);
        float4 v0 = __ldg(&z[(long)c0 * F14 + tid]);
        float4 v1 = __ldg(&z[(long)c1 * F14 + tid]);
        float4 v2 = __ldg(&z[(long)c2 * F14 + tid]);
        float4 v3 = __ldg(&z[(long)c3 * F14 + tid]);
        acc.x += n0 * v0.x + n1 * v1.x + n2 * v2.x + n3 * v3.x;
        acc.y += n0 * v0.y + n1 * v1.y + n2 * v2.y + n3 * v3.y;
        acc.z += n0 * v0.z + n1 * v1.z + n2 * v2.z + n3 * v3.z;
        acc.w += n0 * v0.w + n1 * v1.w + n2 * v2.w + n3 * v3.w;
    }
    for (; e < e1; e++) {
        int   c  = __ldg(&g_ccol[e]);
        float nm = __ldg(&g_cnorm[e]);
        float4 v = __ldg(&z[(long)c * F14 + tid]);
        acc.x += nm * v.x; acc.y += nm * v.y;
        acc.z += nm * v.z; acc.w += nm * v.w;
    }
    if (mode) {
        float4 v0 = __ldg(&x0[(long)n * F14 + tid]);
        acc.x = 2.f * acc.x - v0.x; acc.y = 2.f * acc.y - v0.y;
        acc.z = 2.f * acc.z - v0.z; acc.w = 2.f * acc.w - v0.w;
    }
    out[(long)n * F14 + tid] = acc;
}

// ---------------- launch -----------------------------------------------------
extern "C" void kernel_launch(void* const* d_in, const int* in_sizes, int n_in,
                              void* d_out, int out_size)
{
    const float* X    = (const float*)d_in[0];
    const int*   ei   = (const int*)  d_in[1];
    const float* ew   = (const float*)d_in[2];
    const float* t1w1 = (const float*)d_in[3];
    const float* t1b1 = (const float*)d_in[4];
    const float* t1w2 = (const float*)d_in[5];
    const float* t1b2 = (const float*)d_in[6];
    const float* t1w3 = (const float*)d_in[7];
    const float* t1b3 = (const float*)d_in[8];
    const float* chw  = (const float*)d_in[9];
    const float* chb  = (const float*)d_in[10];
    const float* t2w1 = (const float*)d_in[11];
    const float* t2b1 = (const float*)d_in[12];
    const float* t2w2 = (const float*)d_in[13];
    const float* t2b2 = (const float*)d_in[14];
    const float* t2w3 = (const float*)d_in[15];
    const float* t2b3 = (const float*)d_in[16];
    const float* gam  = (const float*)d_in[17];
    const float* bet  = (const float*)d_in[18];
    float* out = (float*)d_out;

    void *p_t1, *p_tx1, *p_tx2;
    cudaGetSymbolAddress(&p_t1,  g_t1);
    cudaGetSymbolAddress(&p_tx1, g_tx1);
    cudaGetSymbolAddress(&p_tx2, g_tx2);

    cudaFuncSetAttribute(k_tconv1_hmma, cudaFuncAttributeMaxDynamicSharedMemorySize, SMEM_H1);
    cudaFuncSetAttribute(k_tconv2_bn,   cudaFuncAttributeMaxDynamicSharedMemorySize, SMEM_B2);
    cudaFuncSetAttribute(k_cheb_hmma,   cudaFuncAttributeMaxDynamicSharedMemorySize, SMEM_HC);

    const int NPREP = 9216 + 4608 + 3072;

    k_prep <<<128, 256>>>(ei, ew);
    k_wprep<<<(NPREP + 255) / 256, 256>>>(
        t2w1, t2w2, t2w3, t1w1, t1w2, t1w3, chw);

    k_tconv1_hmma<<<NB_TOTAL * T1 / 128, 512, SMEM_H1>>>(X, t1b1, t1b2, t1b3);

    k_prop<<<NN, F14>>>((const float4*)p_t1,  (float4*)p_tx1, (const float4*)p_t1, 0);
    k_prop<<<NN, F14>>>((const float4*)p_tx1, (float4*)p_tx2, (const float4*)p_t1, 1);

    k_cheb_hmma<<<NB_TOTAL * T1 / 256, 512, SMEM_HC>>>(chb);

    k_tconv2_bn<<<NB_TOTAL * T2 / 96, 384, SMEM_B2>>>(t2b1, t2b2, t2b3, gam, bet, out);
}

// round 16
// speedup vs baseline: 1.0220x; 1.0220x over previous
#include <cuda_runtime.h>
#include <cuda_bf16.h>
#include <math.h>
#include <stdint.h>

#define BB   2
#define TT   16
#define NN   2048
#define CI1  32
#define CHH  64
#define EE   32768
#define T1   14
#define T2   12
#define F1   (BB*T1*CHH)
#define F14  (F1/4)
#define NB_TOTAL (NN*BB)

__device__ __forceinline__ uint32_t pkbf2(float a, float b) {
    __nv_bfloat162 h = __floats2bfloat162_rn(a, b);
    return *reinterpret_cast<uint32_t*>(&h);
}
__device__ __forceinline__ void mma_bf16(float* d, const uint32_t* a,
                                         uint32_t b0, uint32_t b1) {
    asm volatile(
        "mma.sync.aligned.m16n8k16.row.col.f32.bf16.bf16.f32 "
        "{%0,%1,%2,%3}, {%4,%5,%6,%7}, {%8,%9}, {%0,%1,%2,%3};"
        : "+f"(d[0]), "+f"(d[1]), "+f"(d[2]), "+f"(d[3])
        : "r"(a[0]), "r"(a[1]), "r"(a[2]), "r"(a[3]), "r"(b0), "r"(b1));
}

// ---------------- scratch ----------------------------------------------------
__device__ __align__(16) float g_t1 [NB_TOTAL*T1*CHH];
__device__ __align__(16) float g_tx1[NB_TOTAL*T1*CHH];
__device__ __align__(16) float g_tx2[NB_TOTAL*T1*CHH];
__device__ __align__(16) float g_t2 [NB_TOTAL*T1*CHH];
__device__ float g_deg[NN];
__device__ float g_dis[NN];
__device__ int   g_rowcount[NN];
__device__ int   g_rowstart[NN+1];
__device__ int   g_cursor[NN];
__device__ int   g_ccol[EE];
__device__ float g_cnorm[EE];
// fragment-order packed B weights (uint2 {b0,b1} per (ntile, ks, lane)):
__device__ __align__(16) uint2 g_bh[3*24*4*32];
__device__ __align__(16) uint2 g_bl[3*24*4*32];
__device__ __align__(16) uint2 g_b1h[24*6*32];
__device__ __align__(16) uint2 g_b1l[24*6*32];
__device__ __align__(16) uint2 g_chh[3*8*4*32];
__device__ __align__(16) uint2 g_chl[3*8*4*32];

// ---------------- graph preprocessing (multi-block, R14-proven) --------------
__global__ void k_zero() {
    int i = blockIdx.x * blockDim.x + threadIdx.x;
    if (i < NN) { g_deg[i] = 0.f; g_rowcount[i] = 0; g_cursor[i] = 0; }
}

__global__ void k_deg(const int* __restrict__ ei, const float* __restrict__ ew) {
    int e = blockIdx.x * blockDim.x + threadIdx.x;
    if (e < EE) {
        int r = ei[e], c = ei[EE + e];
        float w = (r == c) ? 0.f : ew[e];
        atomicAdd(&g_deg[r], w);
        atomicAdd(&g_rowcount[r], 1);
    }
}

__global__ void k_scandis() {
    int tid = threadIdx.x;
    for (int i = tid; i < NN; i += 1024) {
        float d = g_deg[i];
        g_dis[i] = (d > 0.f) ? rsqrtf(d) : 0.f;
    }
    int v0 = g_rowcount[2 * tid], v1 = g_rowcount[2 * tid + 1];
    int s  = v0 + v1;
    int lane = tid & 31, wid = tid >> 5;
    int sc = s;
#pragma unroll
    for (int o = 1; o < 32; o <<= 1) {
        int t = __shfl_up_sync(0xffffffffu, sc, o);
        if (lane >= o) sc += t;
    }
    __shared__ int ws[32];
    if (lane == 31) ws[wid] = sc;
    __syncthreads();
    if (wid == 0) {
        int w = ws[lane];
#pragma unroll
        for (int o = 1; o < 32; o <<= 1) {
            int t = __shfl_up_sync(0xffffffffu, w, o);
            if (lane >= o) w += t;
        }
        ws[lane] = w;
    }
    __syncthreads();
    int base = ((wid > 0) ? ws[wid - 1] : 0) + sc - s;
    g_rowstart[2 * tid + 1] = base + v0;
    g_rowstart[2 * tid + 2] = base + v0 + v1;
    if (tid == 0) g_rowstart[0] = 0;
}

__global__ void k_scatter(const int* __restrict__ ei, const float* __restrict__ ew) {
    int e = blockIdx.x * blockDim.x + threadIdx.x;
    if (e < EE) {
        int r = ei[e], c = ei[EE + e];
        float w = (r == c) ? 0.f : ew[e];
        int pos = g_rowstart[r] + atomicAdd(&g_cursor[r], 1);
        g_ccol[pos]  = c;
        g_cnorm[pos] = -g_dis[r] * w * g_dis[c];
    }
}

// ---------------- weight prep: pack B into mma fragment order ----------------
__global__ void k_wprep(const float* __restrict__ w1, const float* __restrict__ w2,
                        const float* __restrict__ w3,
                        const float* __restrict__ v1, const float* __restrict__ v2,
                        const float* __restrict__ v3,
                        const float* __restrict__ cw) {
    int idx = blockIdx.x * blockDim.x + threadIdx.x;
    if (idx < 9216) {                               // tconv2
        int lane = idx & 31;
        int rest = idx >> 5;
        int ks = rest & 3; rest >>= 2;
        int nti = rest % 24;
        int kc  = rest / 24;
        int n  = nti * 8 + (lane >> 2);
        int k0 = ks * 16 + 2 * (lane & 3);
        int j = n / 64, co = n % 64;
        const float* wj = (j == 0) ? w1 : ((j == 1) ? w2 : w3);
        float v00 = wj[(co * 64 + k0    ) * 3 + kc];
        float v01 = wj[(co * 64 + k0 + 1) * 3 + kc];
        float v10 = wj[(co * 64 + k0 + 8) * 3 + kc];
        float v11 = wj[(co * 64 + k0 + 9) * 3 + kc];
        float h00 = __bfloat162float(__float2bfloat16(v00));
        float h01 = __bfloat162float(__float2bfloat16(v01));
        float h10 = __bfloat162float(__float2bfloat16(v10));
        float h11 = __bfloat162float(__float2bfloat16(v11));
        g_bh[idx] = make_uint2(pkbf2(h00, h01), pkbf2(h10, h11));
        g_bl[idx] = make_uint2(pkbf2(v00 - h00, v01 - h01), pkbf2(v10 - h10, v11 - h11));
    }
    int i1 = idx - 9216;                            // tconv1
    if (i1 >= 0 && i1 < 4608) {
        int lane = i1 & 31;
        int rest = i1 >> 5;
        int ks = rest % 6;
        int nti = rest / 6;
        int n  = nti * 8 + (lane >> 2);
        int k0 = ks * 16 + 2 * (lane & 3);
        int j = n / 64, co = n % 64;
        const float* wj = (j == 0) ? v1 : ((j == 1) ? v2 : v3);
        float vv[4];
#pragma unroll
        for (int u = 0; u < 4; u++) {
            int k = k0 + (u >> 1) * 8 + (u & 1);
            int tap = k >> 5, ci = k & 31;
            vv[u] = wj[(co * 32 + ci) * 3 + tap];
        }
        float h0 = __bfloat162float(__float2bfloat16(vv[0]));
        float h1 = __bfloat162float(__float2bfloat16(vv[1]));
        float h2 = __bfloat162float(__float2bfloat16(vv[2]));
        float h3 = __bfloat162float(__float2bfloat16(vv[3]));
        g_b1h[i1] = make_uint2(pkbf2(h0, h1), pkbf2(h2, h3));
        g_b1l[i1] = make_uint2(pkbf2(vv[0] - h0, vv[1] - h1), pkbf2(vv[2] - h2, vv[3] - h3));
    }
    int i2 = i1 - 4608;                             // cheb
    if (i2 >= 0 && i2 < 3072) {
        int lane = i2 & 31;
        int rest = i2 >> 5;
        int ks = rest & 3; rest >>= 2;
        int nti = rest % 8;
        int jj  = rest / 8;
        int co = nti * 8 + (lane >> 2);
        int k0 = ks * 16 + 2 * (lane & 3);
        float v00 = cw[(jj * 64 + k0    ) * 64 + co];
        float v01 = cw[(jj * 64 + k0 + 1) * 64 + co];
        float v10 = cw[(jj * 64 + k0 + 8) * 64 + co];
        float v11 = cw[(jj * 64 + k0 + 9) * 64 + co];
        float h00 = __bfloat162float(__float2bfloat16(v00));
        float h01 = __bfloat162float(__float2bfloat16(v01));
        float h10 = __bfloat162float(__float2bfloat16(v10));
        float h11 = __bfloat162float(__float2bfloat16(v11));
        g_chh[i2] = make_uint2(pkbf2(h00, h01), pkbf2(h10, h11));
        g_chl[i2] = make_uint2(pkbf2(v00 - h00, v01 - h01), pkbf2(v10 - h10, v11 - h11));
    }
}

// =============================================================================
// tconv1 HMMA (R14 proven): M=57344, N=192, K=96; packed-B LDS.64.
// =============================================================================
#define AP1 104
#define O1_AH   768
#define O1_AL   (O1_AH + 128*AP1*2)
#define O1_BH   (O1_AL + 128*AP1*2)
#define O1_BL   (O1_BH + 36864)
#define SMEM_H1 (O1_BL + 36864)

__global__ void __launch_bounds__(512, 1) k_tconv1_hmma(
    const float* __restrict__ x,
    const float* __restrict__ bb1, const float* __restrict__ bb2,
    const float* __restrict__ bb3)
{
    extern __shared__ char smem[];
    float*         sbias = (float*)smem;
    __nv_bfloat16* sAh   = (__nv_bfloat16*)(smem + O1_AH);
    __nv_bfloat16* sAl   = (__nv_bfloat16*)(smem + O1_AL);
    const uint2*   uBH   = (const uint2*)(smem + O1_BH);
    const uint2*   uBL   = (const uint2*)(smem + O1_BL);

    int tid = threadIdx.x;
    if (tid < 64) {
        sbias[tid]       = bb1[tid];
        sbias[64 + tid]  = bb2[tid];
        sbias[128 + tid] = bb3[tid];
    }

    {
        int rA = tid >> 2, quarter = tid & 3;
        long R = (long)blockIdx.x * 128 + rA;
        int nb = (int)(R / 14), t = (int)(R % 14);
        int b = nb & 1, n = nb >> 1;
        const float* xb = x + (long)b * (TT * NN * CI1) + (long)n * CI1;
#pragma unroll
        for (int k4 = 0; k4 < 6; k4++) {
            int k = quarter * 24 + k4 * 4;
            int tap = k >> 5, ci = k & 31;
            float4 v = __ldg((const float4*)(xb + (long)(t + tap) * (NN * CI1) + ci));
            float hx = __bfloat162float(__float2bfloat16(v.x));
            float hy = __bfloat162float(__float2bfloat16(v.y));
            float hz = __bfloat162float(__float2bfloat16(v.z));
            float hw = __bfloat162float(__float2bfloat16(v.w));
            uint32_t off = (uint32_t)rA * (AP1 * 2) + k * 2;
            *(uint2*)((char*)sAh + off) = make_uint2(pkbf2(hx, hy), pkbf2(hz, hw));
            *(uint2*)((char*)sAl + off) = make_uint2(pkbf2(v.x - hx, v.y - hy),
                                                     pkbf2(v.z - hz, v.w - hw));
        }
    }
    for (int u = tid; u < 2304; u += 512) {
        ((uint4*)(smem + O1_BH))[u] = ((const uint4*)g_b1h)[u];
        ((uint4*)(smem + O1_BL))[u] = ((const uint4*)g_b1l)[u];
    }
    __syncthreads();

    int lane = tid & 31, w = tid >> 5;
    int m0 = (w >> 1) * 16;
    int c0 = (w & 1) * 32;
    int g  = lane >> 2, tg = lane & 3;

    float acc[12][4];
#pragma unroll
    for (int nt = 0; nt < 12; nt++)
#pragma unroll
        for (int q = 0; q < 4; q++) acc[nt][q] = 0.f;

#pragma unroll
    for (int ks = 0; ks < 6; ks++) {
        uint32_t ah[4], al[4];
        {
            int row = m0 + g;
            const __nv_bfloat16* ph = sAh + row * AP1 + ks * 16 + 2 * tg;
            const __nv_bfloat16* pl = sAl + row * AP1 + ks * 16 + 2 * tg;
            ah[0] = *(const uint32_t*)(ph);
            ah[1] = *(const uint32_t*)(ph + 8 * AP1);
            ah[2] = *(const uint32_t*)(ph + 8);
            ah[3] = *(const uint32_t*)(ph + 8 * AP1 + 8);
            al[0] = *(const uint32_t*)(pl);
            al[1] = *(const uint32_t*)(pl + 8 * AP1);
            al[2] = *(const uint32_t*)(pl + 8);
            al[3] = *(const uint32_t*)(pl + 8 * AP1 + 8);
        }
#pragma unroll
        for (int nt = 0; nt < 12; nt++) {
            int nti = (nt >> 2) * 8 + (c0 >> 3) + (nt & 3);
            uint2 bh = uBH[(nti * 6 + ks) * 32 + lane];
            uint2 bl = uBL[(nti * 6 + ks) * 32 + lane];
            mma_bf16(acc[nt], ah, bh.x, bh.y);
            mma_bf16(acc[nt], ah, bl.x, bl.y);
            mma_bf16(acc[nt], al, bh.x, bh.y);
        }
    }

#pragma unroll
    for (int rs = 0; rs < 2; rs++) {
        int row = m0 + g + rs * 8;
        long R = (long)blockIdx.x * 128 + row;
        int nb = (int)(R / 14), t = (int)(R % 14);
        float* orow = g_t1 + ((long)nb * T1 + t) * 64;
#pragma unroll
        for (int cb = 0; cb < 4; cb++) {
            int col = c0 + cb * 8 + 2 * tg;
#pragma unroll
            for (int qq = 0; qq < 2; qq++) {
                float a1 = acc[cb][rs * 2 + qq]     + sbias[col + qq];
                float a2 = acc[4 + cb][rs * 2 + qq] + sbias[64 + col + qq];
                float a3 = acc[8 + cb][rs * 2 + qq] + sbias[128 + col + qq];
                float sg = __fdividef(1.f, 1.f + __expf(-a2));
                float v  = a1 + sg + a3;
                orow[col + qq] = (v > 0.f) ? v : 0.f;
            }
        }
    }
}

// =============================================================================
// tconv2 + fused BN: M tiled 96 (=4 whole nodes/block), N=192; grid 512.
// 384 thr = 12 warps (6 m-tiles x 2 c-halves). BN stats in-block, write d_out.
// =============================================================================
#define AP2 72
#define O2_ST   768
#define O2_AH   1024
#define O2_AL   (O2_AH + 96*AP2*2)
#define O2_BH   (O2_AL + 96*AP2*2)
#define O2_BL   (O2_BH + 24576)
#define SMEM_B2 (O2_BL + 24576)

__global__ void __launch_bounds__(384, 1) k_tconv2_bn(
    const float* __restrict__ bb1, const float* __restrict__ bb2,
    const float* __restrict__ bb3,
    const float* __restrict__ gamma, const float* __restrict__ beta,
    float* __restrict__ out)
{
    extern __shared__ char smem[];
    float*         sbias = (float*)smem;
    float*         sstat = (float*)(smem + O2_ST);
    __nv_bfloat16* sAh   = (__nv_bfloat16*)(smem + O2_AH);
    __nv_bfloat16* sAl   = (__nv_bfloat16*)(smem + O2_AL);
    const uint2*   uBH   = (const uint2*)(smem + O2_BH);
    const uint2*   uBL   = (const uint2*)(smem + O2_BL);

    int tid = threadIdx.x;
    if (tid < 64) {
        sbias[tid]       = bb1[tid];
        sbias[64 + tid]  = bb2[tid];
        sbias[128 + tid] = bb3[tid];
    }
    if (tid < 8) sstat[tid] = 0.f;

    int lane = tid & 31, w = tid >> 5;
    int m0 = (w >> 1) * 16;
    int c0 = (w & 1) * 32;
    int g  = lane >> 2, tg = lane & 3;

    int rA = tid >> 2, quarter = tid & 3;
    long RA = (long)blockIdx.x * 96 + rA;
    int nbA = (int)(RA / 12), tA = (int)(RA % 12);

    float acc[12][4];
#pragma unroll
    for (int nt = 0; nt < 12; nt++)
#pragma unroll
        for (int q = 0; q < 4; q++) acc[nt][q] = 0.f;

    for (int kc = 0; kc < 3; kc++) {
        __syncthreads();
        {
            const float4* src = (const float4*)(g_t2 + ((long)nbA * T1 + tA + kc) * 64)
                                + quarter * 4;
            uint32_t off = (uint32_t)rA * (AP2 * 2) + quarter * 32;
            uint2* dh = (uint2*)((char*)sAh + off);
            uint2* dl = (uint2*)((char*)sAl + off);
#pragma unroll
            for (int v4 = 0; v4 < 4; v4++) {
                float4 xv = __ldg(&src[v4]);
                float hx = __bfloat162float(__float2bfloat16(xv.x));
                float hy = __bfloat162float(__float2bfloat16(xv.y));
                float hz = __bfloat162float(__float2bfloat16(xv.z));
                float hw = __bfloat162float(__float2bfloat16(xv.w));
                dh[v4] = make_uint2(pkbf2(hx, hy), pkbf2(hz, hw));
                dl[v4] = make_uint2(pkbf2(xv.x - hx, xv.y - hy),
                                    pkbf2(xv.z - hz, xv.w - hw));
            }
        }
        {
            const uint4* bh = (const uint4*)(g_bh + (long)kc * 3072);
            const uint4* bl = (const uint4*)(g_bl + (long)kc * 3072);
            for (int u = tid; u < 1536; u += 384) {
                ((uint4*)(smem + O2_BH))[u] = bh[u];
                ((uint4*)(smem + O2_BL))[u] = bl[u];
            }
        }
        __syncthreads();

#pragma unroll
        for (int ks = 0; ks < 4; ks++) {
            uint32_t ah[4], al[4];
            {
                int row = m0 + g;
                const __nv_bfloat16* ph = sAh + row * AP2 + ks * 16 + 2 * tg;
                const __nv_bfloat16* pl = sAl + row * AP2 + ks * 16 + 2 * tg;
                ah[0] = *(const uint32_t*)(ph);
                ah[1] = *(const uint32_t*)(ph + 8 * AP2);
                ah[2] = *(const uint32_t*)(ph + 8);
                ah[3] = *(const uint32_t*)(ph + 8 * AP2 + 8);
                al[0] = *(const uint32_t*)(pl);
                al[1] = *(const uint32_t*)(pl + 8 * AP2);
                al[2] = *(const uint32_t*)(pl + 8);
                al[3] = *(const uint32_t*)(pl + 8 * AP2 + 8);
            }
#pragma unroll
            for (int nt = 0; nt < 12; nt++) {
                int nti = (nt >> 2) * 8 + (c0 >> 3) + (nt & 3);
                uint2 bh = uBH[(nti * 4 + ks) * 32 + lane];
                uint2 bl = uBL[(nti * 4 + ks) * 32 + lane];
                mma_bf16(acc[nt], ah, bh.x, bh.y);
                mma_bf16(acc[nt], ah, bl.x, bl.y);
                mma_bf16(acc[nt], al, bh.x, bh.y);
            }
        }
    }

    // ---- gated epilogue in registers + per-node BN stats ----
    float vv[2][4][2];
#pragma unroll
    for (int rs = 0; rs < 2; rs++) {
        int row = m0 + g + rs * 8;
        float s = 0.f, ss = 0.f;
#pragma unroll
        for (int cb = 0; cb < 4; cb++) {
            int col = c0 + cb * 8 + 2 * tg;
#pragma unroll
            for (int qq = 0; qq < 2; qq++) {
                float a1 = acc[cb][rs * 2 + qq]     + sbias[col + qq];
                float a2 = acc[4 + cb][rs * 2 + qq] + sbias[64 + col + qq];
                float a3 = acc[8 + cb][rs * 2 + qq] + sbias[128 + col + qq];
                float sg = __fdividef(1.f, 1.f + __expf(-a2));
                float v  = a1 + sg + a3;
                v = (v > 0.f) ? v : 0.f;
                vv[rs][cb][qq] = v;
                s += v; ss += v * v;
            }
        }
        s  += __shfl_xor_sync(0xffffffffu, s, 1);
        s  += __shfl_xor_sync(0xffffffffu, s, 2);
        ss += __shfl_xor_sync(0xffffffffu, ss, 1);
        ss += __shfl_xor_sync(0xffffffffu, ss, 2);
        if (tg == 0) {
            int nl = row / 24;
            atomicAdd(&sstat[nl], s);
            atomicAdd(&sstat[4 + nl], ss);
        }
    }
    __syncthreads();
    if (tid < 4) {
        float mu  = sstat[tid] * (1.f / 1536.f);
        float var = sstat[4 + tid] * (1.f / 1536.f) - mu * mu;
        sstat[8 + tid]  = mu;
        sstat[12 + tid] = rsqrtf(var + 1e-5f);
    }
    __syncthreads();

#pragma unroll
    for (int rs = 0; rs < 2; rs++) {
        int row = m0 + g + rs * 8;
        long R = (long)blockIdx.x * 96 + row;
        int nb = (int)(R / 12), t = (int)(R % 12);
        int ng = (int)(R / 24);
        int b  = nb & 1;
        int nl = row / 24;
        float mu = sstat[8 + nl], rstd = sstat[12 + nl];
        float ga = __ldg(&gamma[ng]), be = __ldg(&beta[ng]);
        float scale = rstd * ga;
        float* orow = out + (((long)b * T2 + t) * NN + ng) * 64;
#pragma unroll
        for (int cb = 0; cb < 4; cb++) {
            int col = c0 + cb * 8 + 2 * tg;
            float o0 = (vv[rs][cb][0] - mu) * scale + be;
            float o1 = (vv[rs][cb][1] - mu) * scale + be;
            *(float2*)(orow + col) = make_float2(o0, o1);
        }
    }
}

// =============================================================================
// cheb HMMA (R14 proven): M=57344, N=64, K=3 j x 64; block tile M=256.
// =============================================================================
#define APC 72
#define OC_AH   256
#define OC_AL   (OC_AH + 256*APC*2)
#define OC_BH   (OC_AL + 256*APC*2)
#define OC_BL   (OC_BH + 8192)
#define SMEM_HC (OC_BL + 8192)

__global__ void __launch_bounds__(512, 1) k_cheb_hmma(const float* __restrict__ bias)
{
    extern __shared__ char smem[];
    float*         sbias = (float*)smem;
    __nv_bfloat16* sAh   = (__nv_bfloat16*)(smem + OC_AH);
    __nv_bfloat16* sAl   = (__nv_bfloat16*)(smem + OC_AL);
    const uint2*   uBH   = (const uint2*)(smem + OC_BH);
    const uint2*   uBL   = (const uint2*)(smem + OC_BL);

    int tid = threadIdx.x;
    if (tid < 64) sbias[tid] = bias[tid];

    int lane = tid & 31, w = tid >> 5;
    int m0 = w * 16;
    int g  = lane >> 2, tg = lane & 3;

    int rA = tid >> 1, half = tid & 1;
    long RA = (long)blockIdx.x * 256 + rA;

    float acc[8][4];
#pragma unroll
    for (int nt = 0; nt < 8; nt++)
#pragma unroll
        for (int q = 0; q < 4; q++) acc[nt][q] = 0.f;

    for (int j = 0; j < 3; j++) {
        __syncthreads();
        {
            const float* srcj = (j == 0) ? g_t1 : ((j == 1) ? g_tx1 : g_tx2);
            const float4* src = (const float4*)(srcj + RA * 64) + half * 8;
            uint32_t off = (uint32_t)rA * (APC * 2) + half * 64;
            uint2* dh = (uint2*)((char*)sAh + off);
            uint2* dl = (uint2*)((char*)sAl + off);
#pragma unroll
            for (int v4 = 0; v4 < 8; v4++) {
                float4 xv = __ldg(&src[v4]);
                float hx = __bfloat162float(__float2bfloat16(xv.x));
                float hy = __bfloat162float(__float2bfloat16(xv.y));
                float hz = __bfloat162float(__float2bfloat16(xv.z));
                float hw = __bfloat162float(__float2bfloat16(xv.w));
                dh[v4] = make_uint2(pkbf2(hx, hy), pkbf2(hz, hw));
                dl[v4] = make_uint2(pkbf2(xv.x - hx, xv.y - hy),
                                    pkbf2(xv.z - hz, xv.w - hw));
            }
        }
        if (tid < 512) {
            ((uint4*)(smem + OC_BH))[tid] = ((const uint4*)(g_chh + (long)j * 1024))[tid];
            ((uint4*)(smem + OC_BL))[tid] = ((const uint4*)(g_chl + (long)j * 1024))[tid];
        }
        __syncthreads();

#pragma unroll
        for (int ks = 0; ks < 4; ks++) {
            uint32_t ah[4], al[4];
            {
                int row = m0 + g;
                const __nv_bfloat16* ph = sAh + row * APC + ks * 16 + 2 * tg;
                const __nv_bfloat16* pl = sAl + row * APC + ks * 16 + 2 * tg;
                ah[0] = *(const uint32_t*)(ph);
                ah[1] = *(const uint32_t*)(ph + 8 * APC);
                ah[2] = *(const uint32_t*)(ph + 8);
                ah[3] = *(const uint32_t*)(ph + 8 * APC + 8);
                al[0] = *(const uint32_t*)(pl);
                al[1] = *(const uint32_t*)(pl + 8 * APC);
                al[2] = *(const uint32_t*)(pl + 8);
                al[3] = *(const uint32_t*)(pl + 8 * APC + 8);
            }
#pragma unroll
            for (int nt = 0; nt < 8; nt++) {
                uint2 bh = uBH[(nt * 4 + ks) * 32 + lane];
                uint2 bl = uBL[(nt * 4 + ks) * 32 + lane];
                mma_bf16(acc[nt], ah, bh.x, bh.y);
                mma_bf16(acc[nt], ah, bl.x, bl.y);
                mma_bf16(acc[nt], al, bh.x, bh.y);
            }
        }
    }

#pragma unroll
    for (int rs = 0; rs < 2; rs++) {
        int row = m0 + g + rs * 8;
        long R = (long)blockIdx.x * 256 + row;
        float* orow = g_t2 + R * 64;
#pragma unroll
        for (int nt = 0; nt < 8; nt++) {
            int col = nt * 8 + 2 * tg;
            float v0 = acc[nt][rs * 2 + 0] + sbias[col];
            float v1 = acc[nt][rs * 2 + 1] + sbias[col + 1];
            v0 = (v0 > 0.f) ? v0 : 0.f;
            v1 = (v1 > 0.f) ? v1 : 0.f;
            *(float2*)(orow + col) = make_float2(v0, v1);
        }
    }
}

// ---------------- ChebConv propagation (CSR gather, 4x edge unroll) ----------
__global__ void k_prop(const float4* __restrict__ z, float4* __restrict__ out,
                       const float4* __restrict__ x0, int mode)
{
    int n = blockIdx.x;
    int tid = threadIdx.x;
    int e0 = g_rowstart[n], e1 = g_rowstart[n + 1];
    float4 acc = make_float4(0.f, 0.f, 0.f, 0.f);
    int e = e0;
    for (; e + 3 < e1; e += 4) {
        int   c0 = __ldg(&g_ccol[e]),     c1 = __ldg(&g_ccol[e + 1]);
        int   c2 = __ldg(&g_ccol[e + 2]), c3 = __ldg(&g_ccol[e + 3]);
        float n0 = __ldg(&g_cnorm[e]),    n1 = __ldg(&g_cnorm[e + 1]);
        float n2 = __ldg(&g_cnorm[e + 2]), n3 = __ldg(&g_cnorm[e + 3]);
        float4 v0 = __ldg(&z[(long)c0 * F14 + tid]);
        float4 v1 = __ldg(&z[(long)c1 * F14 + tid]);
        float4 v2 = __ldg(&z[(long)c2 * F14 + tid]);
        float4 v3 = __ldg(&z[(long)c3 * F14 + tid]);
        acc.x += n0 * v0.x + n1 * v1.x + n2 * v2.x + n3 * v3.x;
        acc.y += n0 * v0.y + n1 * v1.y + n2 * v2.y + n3 * v3.y;
        acc.z += n0 * v0.z + n1 * v1.z + n2 * v2.z + n3 * v3.z;
        acc.w += n0 * v0.w + n1 * v1.w + n2 * v2.w + n3 * v3.w;
    }
    for (; e < e1; e++) {
        int   c  = __ldg(&g_ccol[e]);
        float nm = __ldg(&g_cnorm[e]);
        float4 v = __ldg(&z[(long)c * F14 + tid]);
        acc.x += nm * v.x; acc.y += nm * v.y;
        acc.z += nm * v.z; acc.w += nm * v.w;
    }
    if (mode) {
        float4 v0 = __ldg(&x0[(long)n * F14 + tid]);
        acc.x = 2.f * acc.x - v0.x; acc.y = 2.f * acc.y - v0.y;
        acc.z = 2.f * acc.z - v0.z; acc.w = 2.f * acc.w - v0.w;
    }
    out[(long)n * F14 + tid] = acc;
}

// ---------------- launch -----------------------------------------------------
extern "C" void kernel_launch(void* const* d_in, const int* in_sizes, int n_in,
                              void* d_out, int out_size)
{
    const float* X    = (const float*)d_in[0];
    const int*   ei   = (const int*)  d_in[1];
    const float* ew   = (const float*)d_in[2];
    const float* t1w1 = (const float*)d_in[3];
    const float* t1b1 = (const float*)d_in[4];
    const float* t1w2 = (const float*)d_in[5];
    const float* t1b2 = (const float*)d_in[6];
    const float* t1w3 = (const float*)d_in[7];
    const float* t1b3 = (const float*)d_in[8];
    const float* chw  = (const float*)d_in[9];
    const float* chb  = (const float*)d_in[10];
    const float* t2w1 = (const float*)d_in[11];
    const float* t2b1 = (const float*)d_in[12];
    const float* t2w2 = (const float*)d_in[13];
    const float* t2b2 = (const float*)d_in[14];
    const float* t2w3 = (const float*)d_in[15];
    const float* t2b3 = (const float*)d_in[16];
    const float* gam  = (const float*)d_in[17];
    const float* bet  = (const float*)d_in[18];
    float* out = (float*)d_out;

    void *p_t1, *p_tx1, *p_tx2;
    cudaGetSymbolAddress(&p_t1,  g_t1);
    cudaGetSymbolAddress(&p_tx1, g_tx1);
    cudaGetSymbolAddress(&p_tx2, g_tx2);

    cudaFuncSetAttribute(k_tconv1_hmma, cudaFuncAttributeMaxDynamicSharedMemorySize, SMEM_H1);
    cudaFuncSetAttribute(k_tconv2_bn,   cudaFuncAttributeMaxDynamicSharedMemorySize, SMEM_B2);
    cudaFuncSetAttribute(k_cheb_hmma,   cudaFuncAttributeMaxDynamicSharedMemorySize, SMEM_HC);

    const int NPREP = 9216 + 4608 + 3072;

    k_zero   <<<(NN + 255) / 256, 256>>>();
    k_deg    <<<EE / 256, 256>>>(ei, ew);
    k_wprep  <<<(NPREP + 255) / 256, 256>>>(
        t2w1, t2w2, t2w3, t1w1, t1w2, t1w3, chw);

    k_tconv1_hmma<<<NB_TOTAL * T1 / 128, 512, SMEM_H1>>>(X, t1b1, t1b2, t1b3);

    k_scandis<<<1, 1024>>>();
    k_scatter<<<EE / 256, 256>>>(ei, ew);

    k_prop<<<NN, F14>>>((const float4*)p_t1,  (float4*)p_tx1, (const float4*)p_t1, 0);
    k_prop<<<NN, F14>>>((const float4*)p_tx1, (float4*)p_tx2, (const float4*)p_t1, 1);

    k_cheb_hmma<<<NB_TOTAL * T1 / 256, 512, SMEM_HC>>>(chb);

    k_tconv2_bn<<<NB_TOTAL * T2 / 96, 384, SMEM_B2>>>(t2b1, t2b2, t2b3, gam, bet, out);
}

// round 17
// speedup vs baseline: 1.0661x; 1.0432x over previous
#include <cuda_runtime.h>
#include <cuda_bf16.h>
#include <math.h>
#include <stdint.h>

#define BB   2
#define TT   16
#define NN   2048
#define CI1  32
#define CHH  64
#define EE   32768
#define T1   14
#define T2   12
#define F1   (BB*T1*CHH)
#define F14  (F1/4)
#define NB_TOTAL (NN*BB)

__device__ __forceinline__ uint32_t pkbf2(float a, float b) {
    __nv_bfloat162 h = __floats2bfloat162_rn(a, b);
    return *reinterpret_cast<uint32_t*>(&h);
}
__device__ __forceinline__ void mma_bf16(float* d, const uint32_t* a,
                                         uint32_t b0, uint32_t b1) {
    asm volatile(
        "mma.sync.aligned.m16n8k16.row.col.f32.bf16.bf16.f32 "
        "{%0,%1,%2,%3}, {%4,%5,%6,%7}, {%8,%9}, {%0,%1,%2,%3};"
        : "+f"(d[0]), "+f"(d[1]), "+f"(d[2]), "+f"(d[3])
        : "r"(a[0]), "r"(a[1]), "r"(a[2]), "r"(a[3]), "r"(b0), "r"(b1));
}

// ---------------- scratch ----------------------------------------------------
__device__ __align__(16) float g_t1 [NB_TOTAL*T1*CHH];
__device__ __align__(16) float g_tx1[NB_TOTAL*T1*CHH];
__device__ __align__(16) float g_tx2[NB_TOTAL*T1*CHH];
__device__ __align__(16) float g_t2 [NB_TOTAL*T1*CHH];
__device__ __align__(16) float g_t3 [NB_TOTAL*T2*CHH];
__device__ float g_deg[NN];
__device__ float g_dis[NN];
__device__ int   g_rowcount[NN];
__device__ int   g_rowstart[NN+1];
__device__ int   g_cursor[NN];
__device__ int   g_ccol[EE];
__device__ float g_cnorm[EE];
// fragment-order packed B weights (uint2 {b0,b1} per (ntile, ks, lane)):
__device__ __align__(16) uint2 g_bh[3*24*4*32];
__device__ __align__(16) uint2 g_bl[3*24*4*32];
__device__ __align__(16) uint2 g_b1h[24*6*32];
__device__ __align__(16) uint2 g_b1l[24*6*32];
__device__ __align__(16) uint2 g_chh[3*8*4*32];
__device__ __align__(16) uint2 g_chl[3*8*4*32];

// ---------------- graph preprocessing (multi-block, R14-proven) --------------
__global__ void k_deg(const int* __restrict__ ei, const float* __restrict__ ew) {
    int e = blockIdx.x * blockDim.x + threadIdx.x;
    if (e < EE) {
        int r = ei[e], c = ei[EE + e];
        float w = (r == c) ? 0.f : ew[e];
        atomicAdd(&g_deg[r], w);
        atomicAdd(&g_rowcount[r], 1);
    }
}

__global__ void k_scandis() {
    int tid = threadIdx.x;
    for (int i = tid; i < NN; i += 1024) {
        float d = g_deg[i];
        g_dis[i] = (d > 0.f) ? rsqrtf(d) : 0.f;
    }
    int v0 = g_rowcount[2 * tid], v1 = g_rowcount[2 * tid + 1];
    int s  = v0 + v1;
    int lane = tid & 31, wid = tid >> 5;
    int sc = s;
#pragma unroll
    for (int o = 1; o < 32; o <<= 1) {
        int t = __shfl_up_sync(0xffffffffu, sc, o);
        if (lane >= o) sc += t;
    }
    __shared__ int ws[32];
    if (lane == 31) ws[wid] = sc;
    __syncthreads();
    if (wid == 0) {
        int w = ws[lane];
#pragma unroll
        for (int o = 1; o < 32; o <<= 1) {
            int t = __shfl_up_sync(0xffffffffu, w, o);
            if (lane >= o) w += t;
        }
        ws[lane] = w;
    }
    __syncthreads();
    int base = ((wid > 0) ? ws[wid - 1] : 0) + sc - s;
    g_rowstart[2 * tid + 1] = base + v0;
    g_rowstart[2 * tid + 2] = base + v0 + v1;
    if (tid == 0) g_rowstart[0] = 0;
}

__global__ void k_scatter(const int* __restrict__ ei, const float* __restrict__ ew) {
    int e = blockIdx.x * blockDim.x + threadIdx.x;
    if (e < EE) {
        int r = ei[e], c = ei[EE + e];
        float w = (r == c) ? 0.f : ew[e];
        int pos = g_rowstart[r] + atomicAdd(&g_cursor[r], 1);
        g_ccol[pos]  = c;
        g_cnorm[pos] = -g_dis[r] * w * g_dis[c];
    }
}

// ---------------- weight prep (+ graph-array zeroing) ------------------------
__global__ void k_wprep(const float* __restrict__ w1, const float* __restrict__ w2,
                        const float* __restrict__ w3,
                        const float* __restrict__ v1, const float* __restrict__ v2,
                        const float* __restrict__ v3,
                        const float* __restrict__ cw) {
    int idx = blockIdx.x * blockDim.x + threadIdx.x;
    if (idx < NN) { g_deg[idx] = 0.f; g_rowcount[idx] = 0; g_cursor[idx] = 0; }
    if (idx < 9216) {                               // tconv2
        int lane = idx & 31;
        int rest = idx >> 5;
        int ks = rest & 3; rest >>= 2;
        int nti = rest % 24;
        int kc  = rest / 24;
        int n  = nti * 8 + (lane >> 2);
        int k0 = ks * 16 + 2 * (lane & 3);
        int j = n / 64, co = n % 64;
        const float* wj = (j == 0) ? w1 : ((j == 1) ? w2 : w3);
        float v00 = wj[(co * 64 + k0    ) * 3 + kc];
        float v01 = wj[(co * 64 + k0 + 1) * 3 + kc];
        float v10 = wj[(co * 64 + k0 + 8) * 3 + kc];
        float v11 = wj[(co * 64 + k0 + 9) * 3 + kc];
        float h00 = __bfloat162float(__float2bfloat16(v00));
        float h01 = __bfloat162float(__float2bfloat16(v01));
        float h10 = __bfloat162float(__float2bfloat16(v10));
        float h11 = __bfloat162float(__float2bfloat16(v11));
        g_bh[idx] = make_uint2(pkbf2(h00, h01), pkbf2(h10, h11));
        g_bl[idx] = make_uint2(pkbf2(v00 - h00, v01 - h01), pkbf2(v10 - h10, v11 - h11));
    }
    int i1 = idx - 9216;                            // tconv1
    if (i1 >= 0 && i1 < 4608) {
        int lane = i1 & 31;
        int rest = i1 >> 5;
        int ks = rest % 6;
        int nti = rest / 6;
        int n  = nti * 8 + (lane >> 2);
        int k0 = ks * 16 + 2 * (lane & 3);
        int j = n / 64, co = n % 64;
        const float* wj = (j == 0) ? v1 : ((j == 1) ? v2 : v3);
        float vv[4];
#pragma unroll
        for (int u = 0; u < 4; u++) {
            int k = k0 + (u >> 1) * 8 + (u & 1);
            int tap = k >> 5, ci = k & 31;
            vv[u] = wj[(co * 32 + ci) * 3 + tap];
        }
        float h0 = __bfloat162float(__float2bfloat16(vv[0]));
        float h1 = __bfloat162float(__float2bfloat16(vv[1]));
        float h2 = __bfloat162float(__float2bfloat16(vv[2]));
        float h3 = __bfloat162float(__float2bfloat16(vv[3]));
        g_b1h[i1] = make_uint2(pkbf2(h0, h1), pkbf2(h2, h3));
        g_b1l[i1] = make_uint2(pkbf2(vv[0] - h0, vv[1] - h1), pkbf2(vv[2] - h2, vv[3] - h3));
    }
    int i2 = i1 - 4608;                             // cheb
    if (i2 >= 0 && i2 < 3072) {
        int lane = i2 & 31;
        int rest = i2 >> 5;
        int ks = rest & 3; rest >>= 2;
        int nti = rest % 8;
        int jj  = rest / 8;
        int co = nti * 8 + (lane >> 2);
        int k0 = ks * 16 + 2 * (lane & 3);
        float v00 = cw[(jj * 64 + k0    ) * 64 + co];
        float v01 = cw[(jj * 64 + k0 + 1) * 64 + co];
        float v10 = cw[(jj * 64 + k0 + 8) * 64 + co];
        float v11 = cw[(jj * 64 + k0 + 9) * 64 + co];
        float h00 = __bfloat162float(__float2bfloat16(v00));
        float h01 = __bfloat162float(__float2bfloat16(v01));
        float h10 = __bfloat162float(__float2bfloat16(v10));
        float h11 = __bfloat162float(__float2bfloat16(v11));
        g_chh[i2] = make_uint2(pkbf2(h00, h01), pkbf2(h10, h11));
        g_chl[i2] = make_uint2(pkbf2(v00 - h00, v01 - h01), pkbf2(v10 - h10, v11 - h11));
    }
}

// =============================================================================
// tconv1 HMMA (R14 proven): M=57344, N=192, K=96; packed-B LDS.64.
// =============================================================================
#define AP1 104
#define O1_AH   768
#define O1_AL   (O1_AH + 128*AP1*2)
#define O1_BH   (O1_AL + 128*AP1*2)
#define O1_BL   (O1_BH + 36864)
#define SMEM_H1 (O1_BL + 36864)

__global__ void __launch_bounds__(512, 1) k_tconv1_hmma(
    const float* __restrict__ x,
    const float* __restrict__ bb1, const float* __restrict__ bb2,
    const float* __restrict__ bb3)
{
    extern __shared__ char smem[];
    float*         sbias = (float*)smem;
    __nv_bfloat16* sAh   = (__nv_bfloat16*)(smem + O1_AH);
    __nv_bfloat16* sAl   = (__nv_bfloat16*)(smem + O1_AL);
    const uint2*   uBH   = (const uint2*)(smem + O1_BH);
    const uint2*   uBL   = (const uint2*)(smem + O1_BL);

    int tid = threadIdx.x;
    if (tid < 64) {
        sbias[tid]       = bb1[tid];
        sbias[64 + tid]  = bb2[tid];
        sbias[128 + tid] = bb3[tid];
    }

    {
        int rA = tid >> 2, quarter = tid & 3;
        long R = (long)blockIdx.x * 128 + rA;
        int nb = (int)(R / 14), t = (int)(R % 14);
        int b = nb & 1, n = nb >> 1;
        const float* xb = x + (long)b * (TT * NN * CI1) + (long)n * CI1;
#pragma unroll
        for (int k4 = 0; k4 < 6; k4++) {
            int k = quarter * 24 + k4 * 4;
            int tap = k >> 5, ci = k & 31;
            float4 v = __ldg((const float4*)(xb + (long)(t + tap) * (NN * CI1) + ci));
            float hx = __bfloat162float(__float2bfloat16(v.x));
            float hy = __bfloat162float(__float2bfloat16(v.y));
            float hz = __bfloat162float(__float2bfloat16(v.z));
            float hw = __bfloat162float(__float2bfloat16(v.w));
            uint32_t off = (uint32_t)rA * (AP1 * 2) + k * 2;
            *(uint2*)((char*)sAh + off) = make_uint2(pkbf2(hx, hy), pkbf2(hz, hw));
            *(uint2*)((char*)sAl + off) = make_uint2(pkbf2(v.x - hx, v.y - hy),
                                                     pkbf2(v.z - hz, v.w - hw));
        }
    }
    for (int u = tid; u < 2304; u += 512) {
        ((uint4*)(smem + O1_BH))[u] = ((const uint4*)g_b1h)[u];
        ((uint4*)(smem + O1_BL))[u] = ((const uint4*)g_b1l)[u];
    }
    __syncthreads();

    int lane = tid & 31, w = tid >> 5;
    int m0 = (w >> 1) * 16;
    int c0 = (w & 1) * 32;
    int g  = lane >> 2, tg = lane & 3;

    float acc[12][4];
#pragma unroll
    for (int nt = 0; nt < 12; nt++)
#pragma unroll
        for (int q = 0; q < 4; q++) acc[nt][q] = 0.f;

#pragma unroll
    for (int ks = 0; ks < 6; ks++) {
        uint32_t ah[4], al[4];
        {
            int row = m0 + g;
            const __nv_bfloat16* ph = sAh + row * AP1 + ks * 16 + 2 * tg;
            const __nv_bfloat16* pl = sAl + row * AP1 + ks * 16 + 2 * tg;
            ah[0] = *(const uint32_t*)(ph);
            ah[1] = *(const uint32_t*)(ph + 8 * AP1);
            ah[2] = *(const uint32_t*)(ph + 8);
            ah[3] = *(const uint32_t*)(ph + 8 * AP1 + 8);
            al[0] = *(const uint32_t*)(pl);
            al[1] = *(const uint32_t*)(pl + 8 * AP1);
            al[2] = *(const uint32_t*)(pl + 8);
            al[3] = *(const uint32_t*)(pl + 8 * AP1 + 8);
        }
#pragma unroll
        for (int nt = 0; nt < 12; nt++) {
            int nti = (nt >> 2) * 8 + (c0 >> 3) + (nt & 3);
            uint2 bh = uBH[(nti * 6 + ks) * 32 + lane];
            uint2 bl = uBL[(nti * 6 + ks) * 32 + lane];
            mma_bf16(acc[nt], ah, bh.x, bh.y);
            mma_bf16(acc[nt], ah, bl.x, bl.y);
            mma_bf16(acc[nt], al, bh.x, bh.y);
        }
    }

#pragma unroll
    for (int rs = 0; rs < 2; rs++) {
        int row = m0 + g + rs * 8;
        long R = (long)blockIdx.x * 128 + row;
        int nb = (int)(R / 14), t = (int)(R % 14);
        float* orow = g_t1 + ((long)nb * T1 + t) * 64;
#pragma unroll
        for (int cb = 0; cb < 4; cb++) {
            int col = c0 + cb * 8 + 2 * tg;
#pragma unroll
            for (int qq = 0; qq < 2; qq++) {
                float a1 = acc[cb][rs * 2 + qq]     + sbias[col + qq];
                float a2 = acc[4 + cb][rs * 2 + qq] + sbias[64 + col + qq];
                float a3 = acc[8 + cb][rs * 2 + qq] + sbias[128 + col + qq];
                float sg = __fdividef(1.f, 1.f + __expf(-a2));
                float v  = a1 + sg + a3;
                orow[col + qq] = (v > 0.f) ? v : 0.f;
            }
        }
    }
}

// =============================================================================
// tconv2 HMMA (R14 proven): M=49152, N=192, K=3 kc x 64; packed-B LDS.64.
// =============================================================================
#define AP2 72
#define O2_AH   768
#define O2_AL   (O2_AH + 128*AP2*2)
#define O2_BH   (O2_AL + 128*AP2*2)
#define O2_BL   (O2_BH + 24576)
#define SMEM_H2 (O2_BL + 24576)

__global__ void __launch_bounds__(512, 1) k_tconv2_hmma(
    const float* __restrict__ bb1, const float* __restrict__ bb2,
    const float* __restrict__ bb3)
{
    extern __shared__ char smem[];
    float*         sbias = (float*)smem;
    __nv_bfloat16* sAh   = (__nv_bfloat16*)(smem + O2_AH);
    __nv_bfloat16* sAl   = (__nv_bfloat16*)(smem + O2_AL);
    const uint2*   uBH   = (const uint2*)(smem + O2_BH);
    const uint2*   uBL   = (const uint2*)(smem + O2_BL);

    int tid = threadIdx.x;
    if (tid < 64) {
        sbias[tid]       = bb1[tid];
        sbias[64 + tid]  = bb2[tid];
        sbias[128 + tid] = bb3[tid];
    }

    int lane = tid & 31, w = tid >> 5;
    int m0 = (w >> 1) * 16;
    int c0 = (w & 1) * 32;
    int g  = lane >> 2, tg = lane & 3;

    int rA = tid >> 2, quarter = tid & 3;
    long RA = (long)blockIdx.x * 128 + rA;
    int nbA = (int)(RA / 12), tA = (int)(RA % 12);

    float acc[12][4];
#pragma unroll
    for (int nt = 0; nt < 12; nt++)
#pragma unroll
        for (int q = 0; q < 4; q++) acc[nt][q] = 0.f;

    for (int kc = 0; kc < 3; kc++) {
        __syncthreads();
        {
            const float4* src = (const float4*)(g_t2 + ((long)nbA * T1 + tA + kc) * 64)
                                + quarter * 4;
            uint32_t off = (uint32_t)rA * (AP2 * 2) + quarter * 32;
            uint2* dh = (uint2*)((char*)sAh + off);
            uint2* dl = (uint2*)((char*)sAl + off);
#pragma unroll
            for (int v4 = 0; v4 < 4; v4++) {
                float4 xv = __ldg(&src[v4]);
                float hx = __bfloat162float(__float2bfloat16(xv.x));
                float hy = __bfloat162float(__float2bfloat16(xv.y));
                float hz = __bfloat162float(__float2bfloat16(xv.z));
                float hw = __bfloat162float(__float2bfloat16(xv.w));
                dh[v4] = make_uint2(pkbf2(hx, hy), pkbf2(hz, hw));
                dl[v4] = make_uint2(pkbf2(xv.x - hx, xv.y - hy),
                                    pkbf2(xv.z - hz, xv.w - hw));
            }
        }
        {
            const uint4* bh = (const uint4*)(g_bh + (long)kc * 3072);
            const uint4* bl = (const uint4*)(g_bl + (long)kc * 3072);
            for (int u = tid; u < 1536; u += 512) {
                ((uint4*)(smem + O2_BH))[u] = bh[u];
                ((uint4*)(smem + O2_BL))[u] = bl[u];
            }
        }
        __syncthreads();

#pragma unroll
        for (int ks = 0; ks < 4; ks++) {
            uint32_t ah[4], al[4];
            {
                int row = m0 + g;
                const __nv_bfloat16* ph = sAh + row * AP2 + ks * 16 + 2 * tg;
                const __nv_bfloat16* pl = sAl + row * AP2 + ks * 16 + 2 * tg;
                ah[0] = *(const uint32_t*)(ph);
                ah[1] = *(const uint32_t*)(ph + 8 * AP2);
                ah[2] = *(const uint32_t*)(ph + 8);
                ah[3] = *(const uint32_t*)(ph + 8 * AP2 + 8);
                al[0] = *(const uint32_t*)(pl);
                al[1] = *(const uint32_t*)(pl + 8 * AP2);
                al[2] = *(const uint32_t*)(pl + 8);
                al[3] = *(const uint32_t*)(pl + 8 * AP2 + 8);
            }
#pragma unroll
            for (int nt = 0; nt < 12; nt++) {
                int nti = (nt >> 2) * 8 + (c0 >> 3) + (nt & 3);
                uint2 bh = uBH[(nti * 4 + ks) * 32 + lane];
                uint2 bl = uBL[(nti * 4 + ks) * 32 + lane];
                mma_bf16(acc[nt], ah, bh.x, bh.y);
                mma_bf16(acc[nt], ah, bl.x, bl.y);
                mma_bf16(acc[nt], al, bh.x, bh.y);
            }
        }
    }

#pragma unroll
    for (int rs = 0; rs < 2; rs++) {
        int row = m0 + g + rs * 8;
        long R = (long)blockIdx.x * 128 + row;
        int nb = (int)(R / 12), t = (int)(R % 12);
        float* orow = g_t3 + ((long)nb * T2 + t) * 64;
#pragma unroll
        for (int cb = 0; cb < 4; cb++) {
            int col = c0 + cb * 8 + 2 * tg;
#pragma unroll
            for (int qq = 0; qq < 2; qq++) {
                float a1 = acc[cb][rs * 2 + qq]     + sbias[col + qq];
                float a2 = acc[4 + cb][rs * 2 + qq] + sbias[64 + col + qq];
                float a3 = acc[8 + cb][rs * 2 + qq] + sbias[128 + col + qq];
                float sg = __fdividef(1.f, 1.f + __expf(-a2));
                float v  = a1 + sg + a3;
                orow[col + qq] = (v > 0.f) ? v : 0.f;
            }
        }
    }
}

// =============================================================================
// cheb HMMA (R14 proven): M=57344, N=64, K=3 j x 64; block tile M=256.
// =============================================================================
#define APC 72
#define OC_AH   256
#define OC_AL   (OC_AH + 256*APC*2)
#define OC_BH   (OC_AL + 256*APC*2)
#define OC_BL   (OC_BH + 8192)
#define SMEM_HC (OC_BL + 8192)

__global__ void __launch_bounds__(512, 1) k_cheb_hmma(const float* __restrict__ bias)
{
    extern __shared__ char smem[];
    float*         sbias = (float*)smem;
    __nv_bfloat16* sAh   = (__nv_bfloat16*)(smem + OC_AH);
    __nv_bfloat16* sAl   = (__nv_bfloat16*)(smem + OC_AL);
    const uint2*   uBH   = (const uint2*)(smem + OC_BH);
    const uint2*   uBL   = (const uint2*)(smem + OC_BL);

    int tid = threadIdx.x;
    if (tid < 64) sbias[tid] = bias[tid];

    int lane = tid & 31, w = tid >> 5;
    int m0 = w * 16;
    int g  = lane >> 2, tg = lane & 3;

    int rA = tid >> 1, half = tid & 1;
    long RA = (long)blockIdx.x * 256 + rA;

    float acc[8][4];
#pragma unroll
    for (int nt = 0; nt < 8; nt++)
#pragma unroll
        for (int q = 0; q < 4; q++) acc[nt][q] = 0.f;

    for (int j = 0; j < 3; j++) {
        __syncthreads();
        {
            const float* srcj = (j == 0) ? g_t1 : ((j == 1) ? g_tx1 : g_tx2);
            const float4* src = (const float4*)(srcj + RA * 64) + half * 8;
            uint32_t off = (uint32_t)rA * (APC * 2) + half * 64;
            uint2* dh = (uint2*)((char*)sAh + off);
            uint2* dl = (uint2*)((char*)sAl + off);
#pragma unroll
            for (int v4 = 0; v4 < 8; v4++) {
                float4 xv = __ldg(&src[v4]);
                float hx = __bfloat162float(__float2bfloat16(xv.x));
                float hy = __bfloat162float(__float2bfloat16(xv.y));
                float hz = __bfloat162float(__float2bfloat16(xv.z));
                float hw = __bfloat162float(__float2bfloat16(xv.w));
                dh[v4] = make_uint2(pkbf2(hx, hy), pkbf2(hz, hw));
                dl[v4] = make_uint2(pkbf2(xv.x - hx, xv.y - hy),
                                    pkbf2(xv.z - hz, xv.w - hw));
            }
        }
        if (tid < 512) {
            ((uint4*)(smem + OC_BH))[tid] = ((const uint4*)(g_chh + (long)j * 1024))[tid];
            ((uint4*)(smem + OC_BL))[tid] = ((const uint4*)(g_chl + (long)j * 1024))[tid];
        }
        __syncthreads();

#pragma unroll
        for (int ks = 0; ks < 4; ks++) {
            uint32_t ah[4], al[4];
            {
                int row = m0 + g;
                const __nv_bfloat16* ph = sAh + row * APC + ks * 16 + 2 * tg;
                const __nv_bfloat16* pl = sAl + row * APC + ks * 16 + 2 * tg;
                ah[0] = *(const uint32_t*)(ph);
                ah[1] = *(const uint32_t*)(ph + 8 * APC);
                ah[2] = *(const uint32_t*)(ph + 8);
                ah[3] = *(const uint32_t*)(ph + 8 * APC + 8);
                al[0] = *(const uint32_t*)(pl);
                al[1] = *(const uint32_t*)(pl + 8 * APC);
                al[2] = *(const uint32_t*)(pl + 8);
                al[3] = *(const uint32_t*)(pl + 8 * APC + 8);
            }
#pragma unroll
            for (int nt = 0; nt < 8; nt++) {
                uint2 bh = uBH[(nt * 4 + ks) * 32 + lane];
                uint2 bl = uBL[(nt * 4 + ks) * 32 + lane];
                mma_bf16(acc[nt], ah, bh.x, bh.y);
                mma_bf16(acc[nt], ah, bl.x, bl.y);
                mma_bf16(acc[nt], al, bh.x, bh.y);
            }
        }
    }

#pragma unroll
    for (int rs = 0; rs < 2; rs++) {
        int row = m0 + g + rs * 8;
        long R = (long)blockIdx.x * 256 + row;
        float* orow = g_t2 + R * 64;
#pragma unroll
        for (int nt = 0; nt < 8; nt++) {
            int col = nt * 8 + 2 * tg;
            float v0 = acc[nt][rs * 2 + 0] + sbias[col];
            float v1 = acc[nt][rs * 2 + 1] + sbias[col + 1];
            v0 = (v0 > 0.f) ? v0 : 0.f;
            v1 = (v1 > 0.f) ? v1 : 0.f;
            *(float2*)(orow + col) = make_float2(v0, v1);
        }
    }
}

// ---------------- ChebConv propagation (CSR gather, 4x edge unroll) ----------
__global__ void k_prop(const float4* __restrict__ z, float4* __restrict__ out,
                       const float4* __restrict__ x0, int mode)
{
    int n = blockIdx.x;
    int tid = threadIdx.x;
    int e0 = g_rowstart[n], e1 = g_rowstart[n + 1];
    float4 acc = make_float4(0.f, 0.f, 0.f, 0.f);
    int e = e0;
    for (; e + 3 < e1; e += 4) {
        int   c0 = __ldg(&g_ccol[e]),     c1 = __ldg(&g_ccol[e + 1]);
        int   c2 = __ldg(&g_ccol[e + 2]), c3 = __ldg(&g_ccol[e + 3]);
        float n0 = __ldg(&g_cnorm[e]),    n1 = __ldg(&g_cnorm[e + 1]);
        float n2 = __ldg(&g_cnorm[e + 2]), n3 = __ldg(&g_cnorm[e + 3]);
        float4 v0 = __ldg(&z[(long)c0 * F14 + tid]);
        float4 v1 = __ldg(&z[(long)c1 * F14 + tid]);
        float4 v2 = __ldg(&z[(long)c2 * F14 + tid]);
        float4 v3 = __ldg(&z[(long)c3 * F14 + tid]);
        acc.x += n0 * v0.x + n1 * v1.x + n2 * v2.x + n3 * v3.x;
        acc.y += n0 * v0.y + n1 * v1.y + n2 * v2.y + n3 * v3.y;
        acc.z += n0 * v0.z + n1 * v1.z + n2 * v2.z + n3 * v3.z;
        acc.w += n0 * v0.w + n1 * v1.w + n2 * v2.w + n3 * v3.w;
    }
    for (; e < e1; e++) {
        int   c  = __ldg(&g_ccol[e]);
        float nm = __ldg(&g_cnorm[e]);
        float4 v = __ldg(&z[(long)c * F14 + tid]);
        acc.x += nm * v.x; acc.y += nm * v.y;
        acc.z += nm * v.z; acc.w += nm * v.w;
    }
    if (mode) {
        float4 v0 = __ldg(&x0[(long)n * F14 + tid]);
        acc.x = 2.f * acc.x - v0.x; acc.y = 2.f * acc.y - v0.y;
        acc.z = 2.f * acc.z - v0.z; acc.w = 2.f * acc.w - v0.w;
    }
    out[(long)n * F14 + tid] = acc;
}

// ---------------- BN (channel axis = node) + final transpose -----------------
__global__ void k_bn(const float* __restrict__ gamma, const float* __restrict__ beta,
                     float* __restrict__ out)
{
    int n = blockIdx.x;
    const float* tp = g_t3 + (long)n * (BB * T2 * 64);
    float s = 0.f, s2 = 0.f;
    for (int i = threadIdx.x; i < BB * T2 * 64; i += 256) {
        float v = tp[i]; s += v; s2 += v * v;
    }
    __shared__ float rs[8], rs2[8];
    for (int o = 16; o; o >>= 1) {
        s  += __shfl_down_sync(0xffffffff, s,  o);
        s2 += __shfl_down_sync(0xffffffff, s2, o);
    }
    int lane = threadIdx.x & 31, wid = threadIdx.x >> 5;
    if (lane == 0) { rs[wid] = s; rs2[wid] = s2; }
    __syncthreads();
    __shared__ float smu, srstd;
    if (wid == 0) {
        float a  = (lane < 8) ? rs[lane]  : 0.f;
        float a2 = (lane < 8) ? rs2[lane] : 0.f;
        for (int o = 4; o; o >>= 1) {
            a  += __shfl_down_sync(0xffffffff, a,  o);
            a2 += __shfl_down_sync(0xffffffff, a2, o);
        }
        if (lane == 0) {
            float mu  = a / 1536.f;
            float var = a2 / 1536.f - mu * mu;
            smu = mu; srstd = rsqrtf(var + 1e-5f);
        }
    }
    __syncthreads();
    float mu = smu, rstd = srstd;
    float ga = gamma[n], be = beta[n];
    for (int i = threadIdx.x; i < BB * T2 * 64; i += 256) {
        float v = (tp[i] - mu) * rstd * ga + be;
        int c = i & 63;
        int t = (i >> 6) % T2;
        int b = i / (T2 * 64);
        out[(((long)b * T2 + t) * NN + n) * 64 + c] = v;
    }
}

// ---------------- launch -----------------------------------------------------
extern "C" void kernel_launch(void* const* d_in, const int* in_sizes, int n_in,
                              void* d_out, int out_size)
{
    const float* X    = (const float*)d_in[0];
    const int*   ei   = (const int*)  d_in[1];
    const float* ew   = (const float*)d_in[2];
    const float* t1w1 = (const float*)d_in[3];
    const float* t1b1 = (const float*)d_in[4];
    const float* t1w2 = (const float*)d_in[5];
    const float* t1b2 = (const float*)d_in[6];
    const float* t1w3 = (const float*)d_in[7];
    const float* t1b3 = (const float*)d_in[8];
    const float* chw  = (const float*)d_in[9];
    const float* chb  = (const float*)d_in[10];
    const float* t2w1 = (const float*)d_in[11];
    const float* t2b1 = (const float*)d_in[12];
    const float* t2w2 = (const float*)d_in[13];
    const float* t2b2 = (const float*)d_in[14];
    const float* t2w3 = (const float*)d_in[15];
    const float* t2b3 = (const float*)d_in[16];
    const float* gam  = (const float*)d_in[17];
    const float* bet  = (const float*)d_in[18];
    float* out = (float*)d_out;

    void *p_t1, *p_tx1, *p_tx2;
    cudaGetSymbolAddress(&p_t1,  g_t1);
    cudaGetSymbolAddress(&p_tx1, g_tx1);
    cudaGetSymbolAddress(&p_tx2, g_tx2);

    cudaFuncSetAttribute(k_tconv1_hmma, cudaFuncAttributeMaxDynamicSharedMemorySize, SMEM_H1);
    cudaFuncSetAttribute(k_tconv2_hmma, cudaFuncAttributeMaxDynamicSharedMemorySize, SMEM_H2);
    cudaFuncSetAttribute(k_cheb_hmma,   cudaFuncAttributeMaxDynamicSharedMemorySize, SMEM_HC);

    const int NPREP = 9216 + 4608 + 3072;   // 16896 (>= NN for zeroing)

    k_wprep  <<<(NPREP + 255) / 256, 256>>>(
        t2w1, t2w2, t2w3, t1w1, t1w2, t1w3, chw);   // also zeroes graph arrays
    k_deg    <<<EE / 256, 256>>>(ei, ew);

    k_tconv1_hmma<<<NB_TOTAL * T1 / 128, 512, SMEM_H1>>>(X, t1b1, t1b2, t1b3);

    k_scandis<<<1, 1024>>>();
    k_scatter<<<EE / 256, 256>>>(ei, ew);

    k_prop<<<NN, F14>>>((const float4*)p_t1,  (float4*)p_tx1, (const float4*)p_t1, 0);
    k_prop<<<NN, F14>>>((const float4*)p_tx1, (float4*)p_tx2, (const float4*)p_t1, 1);

    k_cheb_hmma<<<NB_TOTAL * T1 / 256, 512, SMEM_HC>>>(chb);

    k_tconv2_hmma<<<NB_TOTAL * T2 / 128, 512, SMEM_H2>>>(t2b1, t2b2, t2b3);

    k_bn<<<NN, 256>>>(gam, bet, out);
}